// round 13
// baseline (speedup 1.0000x reference)
#include <cuda_runtime.h>
#include <cuda_fp16.h>
#include <cstdint>
#include <math.h>

// Problem constants
#define B_DIM 4
#define N_DIM 8192
#define M_DIM 8192
#define C_DIM 512
#define H_DIM 8
#define D_DIM 64
#define BH    (B_DIM * H_DIM)     // 32
#define ROWS  (B_DIM * N_DIM)     // 32768

// kv chunking
#define CH2   512
#define NCH2  (M_DIM / CH2)       // 16

// ---------------------------------------------------------------------------
// Scratch (device globals; no allocation in kernel_launch)
// ---------------------------------------------------------------------------
__device__ __half g_Qh [(size_t)B_DIM * N_DIM * C_DIM];
__device__ __half g_Kh [(size_t)B_DIM * M_DIM * C_DIM];
__device__ __half g_Vh [(size_t)B_DIM * M_DIM * C_DIM];
__device__ __half g_xh [(size_t)B_DIM * N_DIM * C_DIM];
__device__ __half g_yh [(size_t)B_DIM * M_DIM * C_DIM];
__device__ __half g_ATTh[(size_t)B_DIM * N_DIM * C_DIM];
__device__ __half g_Wh [4 * C_DIM * C_DIM];
__device__ float  g_kvp [(size_t)BH * NCH2 * D_DIM * D_DIM];
__device__ float  g_ksp [(size_t)BH * NCH2 * D_DIM];
__device__ float  g_kv  [BH * D_DIM * D_DIM];
__device__ float  g_ksum[BH * D_DIM];

// ---------------------------------------------------------------------------
// Helpers
// ---------------------------------------------------------------------------
__device__ __forceinline__ void cp16(uint32_t dst, const void* src) {
    asm volatile("cp.async.cg.shared.global [%0], [%1], 16;" :: "r"(dst), "l"(src));
}
__device__ __forceinline__ uint32_t smem_u32(const void* p) {
    uint32_t a;
    asm("{ .reg .u64 t; cvta.to.shared.u64 t, %1; cvt.u32.u64 %0, t; }"
        : "=r"(a) : "l"(p));
    return a;
}
#define CP_COMMIT() asm volatile("cp.async.commit_group;" ::: "memory")

#define LDSM4(r0, r1, r2, r3, addr) \
    asm volatile("ldmatrix.sync.aligned.m8n8.x4.shared.b16 {%0,%1,%2,%3}, [%4];" \
        : "=r"(r0), "=r"(r1), "=r"(r2), "=r"(r3) : "r"(addr))
#define LDSM4T(r0, r1, r2, r3, addr) \
    asm volatile("ldmatrix.sync.aligned.m8n8.x4.trans.shared.b16 {%0,%1,%2,%3}, [%4];" \
        : "=r"(r0), "=r"(r1), "=r"(r2), "=r"(r3) : "r"(addr))

__device__ __forceinline__ void mma_f16(
    float c[4], const uint32_t a[4], const uint32_t b[2])
{
    asm volatile(
        "mma.sync.aligned.m16n8k16.row.col.f32.f16.f16.f32 "
        "{%0,%1,%2,%3}, {%4,%5,%6,%7}, {%8,%9}, {%0,%1,%2,%3};"
        : "+f"(c[0]), "+f"(c[1]), "+f"(c[2]), "+f"(c[3])
        : "r"(a[0]), "r"(a[1]), "r"(a[2]), "r"(a[3]), "r"(b[0]), "r"(b[1]));
}

__device__ __forceinline__ void store_pair(float* p, float a, float b) {
    *(float2*)p = make_float2(a, b);
}
__device__ __forceinline__ void store_pair(__half* p, float a, float b) {
    *(__half2*)p = __floats2half2_rn(a, b);
}

// ---------------------------------------------------------------------------
// fp32 -> fp16 conversion pre-passes
// ---------------------------------------------------------------------------
__global__ __launch_bounds__(256) void cvt_half_k(
    const float4* __restrict__ in, __half2* __restrict__ out, int n4)
{
    int i = blockIdx.x * blockDim.x + threadIdx.x;
    const int stride = gridDim.x * blockDim.x;
    for (; i < n4; i += stride) {
        float4 v = in[i];
        out[i * 2]     = __floats2half2_rn(v.x, v.y);
        out[i * 2 + 1] = __floats2half2_rn(v.z, v.w);
    }
}

// All 4 weight matrices in one launch (blockIdx.y selects)
__global__ __launch_bounds__(256) void cvt_w4_k(
    const float4* __restrict__ w0, const float4* __restrict__ w1,
    const float4* __restrict__ w2, const float4* __restrict__ w3,
    __half2* __restrict__ out)
{
    const float4* srcs[4] = {w0, w1, w2, w3};
    const float4* in = srcs[blockIdx.y];
    __half2* o = out + (size_t)blockIdx.y * (C_DIM * C_DIM / 2);
    const int n4 = C_DIM * C_DIM / 4;
    for (int i = blockIdx.x * 256 + threadIdx.x; i < n4; i += gridDim.x * 256) {
        float4 v = in[i];
        o[i * 2]     = __floats2half2_rn(v.x, v.y);
        o[i * 2 + 1] = __floats2half2_rn(v.z, v.w);
    }
}

// ---------------------------------------------------------------------------
// GEMM: C[32768 x 512] = A[32768 x 512] @ W[512 x 512] + bias, optional
// per-head softmax fused in epilogue. fp16 mma.sync m16n8k16 + ldmatrix.
// Block 128x128, BK=64, 3-stage cp.async pipeline (8 mainloop stages).
// A smem rows padded to 144B, B rows 272B -> conflict-free ldmatrix.
// ---------------------------------------------------------------------------
#define BK       64
#define NSTG     (C_DIM / BK)     // 8
#define A_ROWB   144
#define B_ROWB   272
#define A_STAGE  (128 * A_ROWB)   // 18432
#define B_STAGE  (BK * B_ROWB)    // 17408
#define GEMM_SMEM (3 * (A_STAGE + B_STAGE))   // 107520

template <bool DO_SOFTMAX, typename TO>
__global__ __launch_bounds__(256, 2) void gemm_mma(
    const __half* __restrict__ A, const __half* __restrict__ W,
    const float* __restrict__ bias, TO* __restrict__ Cw)
{
    extern __shared__ char dsm[];
    const uint32_t aS = smem_u32(dsm);
    const uint32_t bS = aS + 3 * A_STAGE;

    const int tid = threadIdx.x;
    const int bx = blockIdx.x;
    const int by = blockIdx.y;

    const __half* Ab = A + (size_t)by * 128 * C_DIM;
    const __half* Wb = W + bx * 128;

    auto load_stage = [&](int stg) {
        const int buf = stg % 3;
        const int k0 = stg * BK;
        const uint32_t ab = aS + buf * A_STAGE;
        const uint32_t bb = bS + buf * B_STAGE;
        // A: 128 rows x 64 halves = 1024 chunks of 16B
#pragma unroll
        for (int q = 0; q < 4; q++) {
            const int c = tid + q * 256;
            const int row = c >> 3;            // 0..127
            const int ch = c & 7;              // 0..7
            cp16(ab + (uint32_t)(row * A_ROWB + ch * 16),
                 Ab + (size_t)row * C_DIM + k0 + ch * 8);
        }
        // B: 64 k-rows x 128 halves = 1024 chunks of 16B
#pragma unroll
        for (int q = 0; q < 4; q++) {
            const int c = tid + q * 256;
            const int row = c >> 4;            // 0..63
            const int ch = c & 15;             // 0..15
            cp16(bb + (uint32_t)(row * B_ROWB + ch * 16),
                 Wb + (size_t)(k0 + row) * C_DIM + ch * 8);
        }
        CP_COMMIT();
    };

    const int wid  = tid >> 5;
    const int lane = tid & 31;
    const int wm = (wid >> 1) * 32;
    const int wn = (wid & 1) * 64;
    const int g  = lane >> 2;
    const int tg = lane & 3;

    const int l7 = lane & 7;
    const int q1 = (lane >> 3) & 1;
    const int q2 = lane >> 4;
    const uint32_t aLane = aS + (uint32_t)((wm + l7 + q1 * 8) * A_ROWB + q2 * 16);
    const uint32_t bLane = bS + (uint32_t)((l7 + q1 * 8) * B_ROWB + q2 * 16 + wn * 2);

    float acc[2][8][4];
#pragma unroll
    for (int i = 0; i < 2; i++)
#pragma unroll
        for (int j = 0; j < 8; j++)
#pragma unroll
            for (int t = 0; t < 4; t++) acc[i][j][t] = 0.f;

    load_stage(0);
    load_stage(1);

    for (int i = 0; i < NSTG; i++) {
        if (i < NSTG - 1) asm volatile("cp.async.wait_group 1;" ::: "memory");
        else              asm volatile("cp.async.wait_group 0;" ::: "memory");
        __syncthreads();
        if (i + 2 < NSTG) load_stage(i + 2);

        const int buf = i % 3;
        const uint32_t aBuf = aLane + buf * A_STAGE;
        const uint32_t bBuf = bLane + buf * B_STAGE;
#pragma unroll
        for (int kk = 0; kk < 4; kk++) {          // four k16 steps per BK=64
            uint32_t a[2][4];
#pragma unroll
            for (int mt = 0; mt < 2; mt++)
                LDSM4(a[mt][0], a[mt][1], a[mt][2], a[mt][3],
                      aBuf + (uint32_t)(mt * 16 * A_ROWB + kk * 32));
            uint32_t b[8][2];
#pragma unroll
            for (int np = 0; np < 4; np++)
                LDSM4T(b[2 * np][0], b[2 * np][1], b[2 * np + 1][0], b[2 * np + 1][1],
                       bBuf + (uint32_t)(kk * 16 * B_ROWB + np * 32));
#pragma unroll
            for (int mt = 0; mt < 2; mt++)
#pragma unroll
                for (int nt = 0; nt < 8; nt++)
                    mma_f16(acc[mt][nt], a[mt], b[nt]);
        }
    }

    // ---- epilogue: bias (+ optional per-head softmax) + store ----
    float bc[8][2];
#pragma unroll
    for (int nt = 0; nt < 8; nt++) {
        const int col = bx * 128 + wn + nt * 8 + tg * 2;
        bc[nt][0] = __ldg(bias + col);
        bc[nt][1] = __ldg(bias + col + 1);
    }
#pragma unroll
    for (int mt = 0; mt < 2; mt++)
#pragma unroll
        for (int nt = 0; nt < 8; nt++) {
            acc[mt][nt][0] += bc[nt][0];
            acc[mt][nt][1] += bc[nt][1];
            acc[mt][nt][2] += bc[nt][0];
            acc[mt][nt][3] += bc[nt][1];
        }

    if (DO_SOFTMAX) {
#pragma unroll
        for (int mt = 0; mt < 2; mt++) {
            float mxA = -1e30f, mxB = -1e30f;
#pragma unroll
            for (int nt = 0; nt < 8; nt++) {
                mxA = fmaxf(mxA, fmaxf(acc[mt][nt][0], acc[mt][nt][1]));
                mxB = fmaxf(mxB, fmaxf(acc[mt][nt][2], acc[mt][nt][3]));
            }
            mxA = fmaxf(mxA, __shfl_xor_sync(~0u, mxA, 1));
            mxA = fmaxf(mxA, __shfl_xor_sync(~0u, mxA, 2));
            mxB = fmaxf(mxB, __shfl_xor_sync(~0u, mxB, 1));
            mxB = fmaxf(mxB, __shfl_xor_sync(~0u, mxB, 2));
            float sA_ = 0.f, sB_ = 0.f;
#pragma unroll
            for (int nt = 0; nt < 8; nt++) {
                acc[mt][nt][0] = __expf(acc[mt][nt][0] - mxA);
                acc[mt][nt][1] = __expf(acc[mt][nt][1] - mxA);
                acc[mt][nt][2] = __expf(acc[mt][nt][2] - mxB);
                acc[mt][nt][3] = __expf(acc[mt][nt][3] - mxB);
                sA_ += acc[mt][nt][0] + acc[mt][nt][1];
                sB_ += acc[mt][nt][2] + acc[mt][nt][3];
            }
            sA_ += __shfl_xor_sync(~0u, sA_, 1);
            sA_ += __shfl_xor_sync(~0u, sA_, 2);
            sB_ += __shfl_xor_sync(~0u, sB_, 1);
            sB_ += __shfl_xor_sync(~0u, sB_, 2);
            const float invA = 1.0f / sA_;
            const float invB = 1.0f / sB_;
#pragma unroll
            for (int nt = 0; nt < 8; nt++) {
                acc[mt][nt][0] *= invA;
                acc[mt][nt][1] *= invA;
                acc[mt][nt][2] *= invB;
                acc[mt][nt][3] *= invB;
            }
        }
    }

#pragma unroll
    for (int nt = 0; nt < 8; nt++) {
        const int col = bx * 128 + wn + nt * 8 + tg * 2;
#pragma unroll
        for (int mt = 0; mt < 2; mt++) {
            const size_t r0 = (size_t)by * 128 + wm + mt * 16 + g;
            store_pair(Cw + r0 * C_DIM + col, acc[mt][nt][0], acc[mt][nt][1]);
            store_pair(Cw + (r0 + 8) * C_DIM + col, acc[mt][nt][2], acc[mt][nt][3]);
        }
    }
}

// ---------------------------------------------------------------------------
// kv partials with fp16 mma: per (bh, chunk of 512 rows) accumulate K^T V
// (64x64 fp32) + column sums of K (parallelized 4x across 256 threads).
// ---------------------------------------------------------------------------
#define KV_PITCHB 144
#define KV_SLABB  (128 * KV_PITCHB)      // 18432
#define KV_SMEM   (2 * 2 * KV_SLABB)     // 73728

__global__ __launch_bounds__(256) void kv_partial_k()
{
    extern __shared__ char dsm[];
    __shared__ float ksred[4][64];
    const uint32_t sbase = smem_u32(dsm);
    const int bh = blockIdx.x, chunk = blockIdx.y;
    const int b = bh >> 3, h = bh & 7;
    const int tid = threadIdx.x;
    const __half* Kb = g_Kh + ((size_t)b * M_DIM + chunk * CH2) * C_DIM + h * D_DIM;
    const __half* Vb = g_Vh + ((size_t)b * M_DIM + chunk * CH2) * C_DIM + h * D_DIM;

    auto load_slab = [&](int s) {
        const int buf = s & 1;
        const uint32_t kd = sbase + buf * (2 * KV_SLABB);
        const uint32_t vd = kd + KV_SLABB;
        const int m0 = s * 128;
#pragma unroll
        for (int q = 0; q < 4; q++) {
            const int c = tid + q * 256;       // 0..1023
            const int row = c >> 3, ch = c & 7;
            cp16(kd + (uint32_t)(row * KV_PITCHB + ch * 16),
                 Kb + (size_t)(m0 + row) * C_DIM + ch * 8);
            cp16(vd + (uint32_t)(row * KV_PITCHB + ch * 16),
                 Vb + (size_t)(m0 + row) * C_DIM + ch * 8);
        }
        CP_COMMIT();
    };

    const int wid = tid >> 5, lane = tid & 31;
    const int wd = wid >> 2, we = wid & 3;
    const int d0 = wd * 32, e0 = we * 16;
    const int g = lane >> 2, tg = lane & 3;
    const int l7 = lane & 7, q1 = (lane >> 3) & 1, q2 = lane >> 4;

    float acc[2][2][4] = {};

    load_slab(0);
    load_slab(1);

    // ksum partial: 4 row-groups x 64 cols, coalesced global reads
    {
        const int col = tid & 63, rg = tid >> 6;
        float ssum = 0.f;
        const __half* kp = Kb + (size_t)rg * 128 * C_DIM + col;
#pragma unroll 8
        for (int m = 0; m < 128; m++)
            ssum += __half2float(kp[(size_t)m * C_DIM]);
        ksred[rg][col] = ssum;
    }

    const int NSLAB = CH2 / 128;   // 4
    for (int s = 0; s < NSLAB; s++) {
        if (s < NSLAB - 1) asm volatile("cp.async.wait_group 1;" ::: "memory");
        else               asm volatile("cp.async.wait_group 0;" ::: "memory");
        __syncthreads();
        const int buf = s & 1;
        const uint32_t kS = sbase + buf * (2 * KV_SLABB);
        const uint32_t vS = kS + KV_SLABB;
#pragma unroll
        for (int kk = 0; kk < 8; kk++) {
            const int k0 = kk * 16;
            uint32_t a[2][4];
#pragma unroll
            for (int mt = 0; mt < 2; mt++) {
                const uint32_t addr = kS + (uint32_t)((k0 + l7 + q2 * 8) * KV_PITCHB
                                     + (d0 + mt * 16 + q1 * 8) * 2);
                LDSM4T(a[mt][0], a[mt][1], a[mt][2], a[mt][3], addr);
            }
            uint32_t bfr[2][2];
            {
                const uint32_t addr = vS + (uint32_t)((k0 + l7 + q1 * 8) * KV_PITCHB
                                     + (e0 + q2 * 8) * 2);
                LDSM4T(bfr[0][0], bfr[0][1], bfr[1][0], bfr[1][1], addr);
            }
#pragma unroll
            for (int mt = 0; mt < 2; mt++)
#pragma unroll
                for (int nt = 0; nt < 2; nt++)
                    mma_f16(acc[mt][nt], a[mt], bfr[nt]);
        }
        __syncthreads();
        if (s + 2 < NSLAB) load_slab(s + 2);
    }

    float* dst = g_kvp + ((size_t)bh * NCH2 + chunk) * (D_DIM * D_DIM);
#pragma unroll
    for (int mt = 0; mt < 2; mt++)
#pragma unroll
        for (int nt = 0; nt < 2; nt++) {
            const int d = d0 + mt * 16 + g;
            const int e = e0 + nt * 8 + tg * 2;
            *(float2*)(dst + d * 64 + e)       = make_float2(acc[mt][nt][0], acc[mt][nt][1]);
            *(float2*)(dst + (d + 8) * 64 + e) = make_float2(acc[mt][nt][2], acc[mt][nt][3]);
        }

    if (tid < 64)
        g_ksp[((size_t)bh * NCH2 + chunk) * D_DIM + tid] =
            ksred[0][tid] + ksred[1][tid] + ksred[2][tid] + ksred[3][tid];
}

__global__ __launch_bounds__(256) void kv_reduce_k()
{
    const int bh = blockIdx.x;
    const int i = blockIdx.y * 256 + threadIdx.x;   // 0..4095
    const float* src = g_kvp + (size_t)bh * NCH2 * (D_DIM * D_DIM) + i;
    float s = 0.f;
#pragma unroll
    for (int c = 0; c < NCH2; c++) s += src[(size_t)c * (D_DIM * D_DIM)];
    g_kv[bh * (D_DIM * D_DIM) + i] = s;
    if (blockIdx.y == 0 && threadIdx.x < 64) {
        const float* sp = g_ksp + (size_t)bh * NCH2 * D_DIM + threadIdx.x;
        float t = 0.f;
#pragma unroll
        for (int c = 0; c < NCH2; c++) t += sp[c * D_DIM];
        g_ksum[bh * D_DIM + threadIdx.x] = t;
    }
}

// ---------------------------------------------------------------------------
// Attention core: ATT = q @ kv / denom + q   (fp16 in, fp16 out)
// ---------------------------------------------------------------------------
__global__ __launch_bounds__(256) void attn_k()
{
    const int bh = blockIdx.x;
    const int b = bh >> 3, h = bh & 7;
    const int n0 = blockIdx.y * 64;
    __shared__ float kvs[64][64];
    __shared__ float ksums[64];
    __shared__ float qs[64][68];
    const int tid = threadIdx.x;

    {
        const float* kvsrc = g_kv + bh * (D_DIM * D_DIM);
        for (int i = tid; i < 1024; i += 256) {
            int d = i >> 4, c4 = (i & 15) << 2;
            *(float4*)&kvs[d][c4] = *(const float4*)(kvsrc + d * 64 + c4);
        }
        const __half* Qb = g_Qh + ((size_t)b * N_DIM + n0) * C_DIM + h * D_DIM;
        for (int i = tid; i < 1024; i += 256) {
            int m = i >> 4, c4 = (i & 15) << 2;
            uint2 raw = *(const uint2*)(Qb + (size_t)m * C_DIM + c4);
            float2 f0 = __half22float2(*(__half2*)&raw.x);
            float2 f1 = __half22float2(*(__half2*)&raw.y);
            qs[m][c4] = f0.x; qs[m][c4 + 1] = f0.y;
            qs[m][c4 + 2] = f1.x; qs[m][c4 + 3] = f1.y;
        }
        if (tid < 64) ksums[tid] = g_ksum[bh * D_DIM + tid];
    }
    __syncthreads();

    const int r  = tid >> 2;
    const int e0 = (tid & 3) << 4;

    float denom = 0.f;
#pragma unroll
    for (int d = 0; d < 64; d++) denom += qs[r][d] * ksums[d];
    denom = fmaxf(denom, 1e-6f);
    const float inv = 1.0f / denom;

    float acc[16] = {};
    for (int d = 0; d < 64; d++) {
        float qd = qs[r][d];
#pragma unroll
        for (int j = 0; j < 16; j++) acc[j] += qd * kvs[d][e0 + j];
    }

    __half* Ob = g_ATTh + ((size_t)b * N_DIM + n0 + r) * C_DIM + h * D_DIM + e0;
#pragma unroll
    for (int j = 0; j < 16; j += 2) {
        float v0 = acc[j + 0] * inv + qs[r][e0 + j + 0];
        float v1 = acc[j + 1] * inv + qs[r][e0 + j + 1];
        *(__half2*)(Ob + j) = __floats2half2_rn(v0, v1);
    }
}

// ---------------------------------------------------------------------------
// Launch
// ---------------------------------------------------------------------------
template <typename T>
static T* sym_addr(const void* s)
{
    void* p = nullptr;
    cudaGetSymbolAddress(&p, s);
    return (T*)p;
}

extern "C" void kernel_launch(void* const* d_in, const int* in_sizes, int n_in,
                              void* d_out, int out_size)
{
    const float* x  = (const float*)d_in[0];
    const float* y  = (const float*)d_in[1];
    const float* Wq = (const float*)d_in[2];
    const float* bq = (const float*)d_in[3];
    const float* Wk = (const float*)d_in[4];
    const float* bk = (const float*)d_in[5];
    const float* Wv = (const float*)d_in[6];
    const float* bv = (const float*)d_in[7];
    const float* Wp = (const float*)d_in[8];
    const float* bp = (const float*)d_in[9];
    float* out = (float*)d_out;

    __half* Qh   = sym_addr<__half>(g_Qh);
    __half* Kh   = sym_addr<__half>(g_Kh);
    __half* Vh   = sym_addr<__half>(g_Vh);
    __half* xh   = sym_addr<__half>(g_xh);
    __half* yh   = sym_addr<__half>(g_yh);
    __half* ATTh = sym_addr<__half>(g_ATTh);
    __half* Wh   = sym_addr<__half>(g_Wh);

    cudaFuncSetAttribute((const void*)gemm_mma<true, __half>,
                         cudaFuncAttributeMaxDynamicSharedMemorySize, GEMM_SMEM);
    cudaFuncSetAttribute((const void*)gemm_mma<false, __half>,
                         cudaFuncAttributeMaxDynamicSharedMemorySize, GEMM_SMEM);
    cudaFuncSetAttribute((const void*)gemm_mma<false, float>,
                         cudaFuncAttributeMaxDynamicSharedMemorySize, GEMM_SMEM);
    cudaFuncSetAttribute((const void*)kv_partial_k,
                         cudaFuncAttributeMaxDynamicSharedMemorySize, KV_SMEM);

    // fp16 conversion pre-passes (3 launches)
    const int n4 = (int)((size_t)ROWS * C_DIM / 4);
    cvt_half_k<<<4096, 256>>>((const float4*)x, (__half2*)xh, n4);
    cvt_half_k<<<4096, 256>>>((const float4*)y, (__half2*)yh, n4);
    cvt_w4_k<<<dim3(64, 4), 256>>>((const float4*)Wq, (const float4*)Wk,
                                   (const float4*)Wv, (const float4*)Wp,
                                   (__half2*)Wh);

    dim3 ggrid(C_DIM / 128, ROWS / 128);   // (4, 256)

    gemm_mma<true,  __half><<<ggrid, 256, GEMM_SMEM>>>(xh, Wh + 0 * C_DIM * C_DIM, bq, Qh);
    gemm_mma<true,  __half><<<ggrid, 256, GEMM_SMEM>>>(yh, Wh + 1 * C_DIM * C_DIM, bk, Kh);
    gemm_mma<false, __half><<<ggrid, 256, GEMM_SMEM>>>(yh, Wh + 2 * C_DIM * C_DIM, bv, Vh);

    kv_partial_k<<<dim3(BH, NCH2), 256, KV_SMEM>>>();
    kv_reduce_k<<<dim3(BH, 16), 256>>>();

    attn_k<<<dim3(BH, N_DIM / 64), 256>>>();

    gemm_mma<false, float><<<ggrid, 256, GEMM_SMEM>>>(ATTh, Wh + 3 * C_DIM * C_DIM, bp, out);
}

// round 15
// speedup vs baseline: 1.0343x; 1.0343x over previous
#include <cuda_runtime.h>
#include <cuda_fp16.h>
#include <cstdint>
#include <math.h>

// Problem constants
#define B_DIM 4
#define N_DIM 8192
#define M_DIM 8192
#define C_DIM 512
#define H_DIM 8
#define D_DIM 64
#define BH    (B_DIM * H_DIM)     // 32
#define ROWS  (B_DIM * N_DIM)     // 32768

// kv chunking
#define CH2   512
#define NCH2  (M_DIM / CH2)       // 16

// ---------------------------------------------------------------------------
// Scratch (device globals; no allocation in kernel_launch)
// ---------------------------------------------------------------------------
__device__ __half g_Qh [(size_t)B_DIM * N_DIM * C_DIM];
__device__ __half g_Kh [(size_t)B_DIM * M_DIM * C_DIM];
__device__ __half g_Vh [(size_t)B_DIM * M_DIM * C_DIM];
__device__ __half g_xh [(size_t)B_DIM * N_DIM * C_DIM];
__device__ __half g_yh [(size_t)B_DIM * M_DIM * C_DIM];
__device__ __half g_ATTh[(size_t)B_DIM * N_DIM * C_DIM];
__device__ __half g_Wqp [2 * C_DIM * C_DIM];          // Wq, Wp
__device__ __half g_Wkv [C_DIM * 2 * C_DIM];          // [512 rows][Wk|Wv cols]
__device__ float  g_kvp [(size_t)BH * NCH2 * D_DIM * D_DIM];
__device__ float  g_ksp [(size_t)BH * NCH2 * D_DIM];
__device__ float  g_kv  [BH * D_DIM * D_DIM];
__device__ float  g_ksum[BH * D_DIM];

// ---------------------------------------------------------------------------
// Helpers
// ---------------------------------------------------------------------------
__device__ __forceinline__ void cp16(uint32_t dst, const void* src) {
    asm volatile("cp.async.cg.shared.global [%0], [%1], 16;" :: "r"(dst), "l"(src));
}
__device__ __forceinline__ uint32_t smem_u32(const void* p) {
    uint32_t a;
    asm("{ .reg .u64 t; cvta.to.shared.u64 t, %1; cvt.u32.u64 %0, t; }"
        : "=r"(a) : "l"(p));
    return a;
}
#define CP_COMMIT() asm volatile("cp.async.commit_group;" ::: "memory")

#define LDSM4(r0, r1, r2, r3, addr) \
    asm volatile("ldmatrix.sync.aligned.m8n8.x4.shared.b16 {%0,%1,%2,%3}, [%4];" \
        : "=r"(r0), "=r"(r1), "=r"(r2), "=r"(r3) : "r"(addr))
#define LDSM4T(r0, r1, r2, r3, addr) \
    asm volatile("ldmatrix.sync.aligned.m8n8.x4.trans.shared.b16 {%0,%1,%2,%3}, [%4];" \
        : "=r"(r0), "=r"(r1), "=r"(r2), "=r"(r3) : "r"(addr))

__device__ __forceinline__ void mma_f16(
    float c[4], const uint32_t a[4], const uint32_t b[2])
{
    asm volatile(
        "mma.sync.aligned.m16n8k16.row.col.f32.f16.f16.f32 "
        "{%0,%1,%2,%3}, {%4,%5,%6,%7}, {%8,%9}, {%0,%1,%2,%3};"
        : "+f"(c[0]), "+f"(c[1]), "+f"(c[2]), "+f"(c[3])
        : "r"(a[0]), "r"(a[1]), "r"(a[2]), "r"(a[3]), "r"(b[0]), "r"(b[1]));
}

__device__ __forceinline__ void store_pair(float* p, float a, float b) {
    *(float2*)p = make_float2(a, b);
}
__device__ __forceinline__ void store_pair(__half* p, float a, float b) {
    *(__half2*)p = __floats2half2_rn(a, b);
}

// ---------------------------------------------------------------------------
// fp32 -> fp16 conversion pre-passes
// ---------------------------------------------------------------------------
__global__ __launch_bounds__(256) void cvt_half_k(
    const float4* __restrict__ in, __half2* __restrict__ out, int n4)
{
    int i = blockIdx.x * blockDim.x + threadIdx.x;
    const int stride = gridDim.x * blockDim.x;
    for (; i < n4; i += stride) {
        float4 v = in[i];
        out[i * 2]     = __floats2half2_rn(v.x, v.y);
        out[i * 2 + 1] = __floats2half2_rn(v.z, v.w);
    }
}

// Weight conversion: Wq,Wp -> g_Wqp (contiguous); Wk,Wv -> g_Wkv packed
// as [512 rows][1024 cols] = [Wk row | Wv row].
__global__ __launch_bounds__(256) void cvt_w4_k(
    const float4* __restrict__ wq, const float4* __restrict__ wk,
    const float4* __restrict__ wv, const float4* __restrict__ wp,
    __half* __restrict__ wqp, __half* __restrict__ wkv)
{
    const int slot = blockIdx.y;   // 0=Wq, 1=Wp, 2=Wk, 3=Wv
    const float4* in = (slot == 0) ? wq : (slot == 1) ? wp : (slot == 2) ? wk : wv;
    const int n4 = C_DIM * C_DIM / 4;
    for (int i = blockIdx.x * 256 + threadIdx.x; i < n4; i += gridDim.x * 256) {
        float4 v = in[i];
        __half2 h0 = __floats2half2_rn(v.x, v.y);
        __half2 h1 = __floats2half2_rn(v.z, v.w);
        if (slot < 2) {
            __half2* o = (__half2*)(wqp + (size_t)slot * C_DIM * C_DIM) + i * 2;
            o[0] = h0; o[1] = h1;
        } else {
            const int e = i * 4;
            const int k = e >> 9;            // row
            const int n = e & 511;           // col within matrix
            __half2* o = (__half2*)(wkv + (size_t)k * 1024 + n + (slot == 3 ? 512 : 0));
            o[0] = h0; o[1] = h1;
        }
    }
}

// ---------------------------------------------------------------------------
// GEMM: block 128x128, BK=32, 3-stage cp.async (round-12 proven config).
// fp16 mma.sync m16n8k16 + ldmatrix; optional fused per-head softmax.
// ---------------------------------------------------------------------------
#define BK       32
#define NSTG     (C_DIM / BK)     // 16
#define A_ROWB   80
#define B_ROWB   272
#define A_STAGE  (128 * A_ROWB)   // 10240
#define B_STAGE  (BK * B_ROWB)    // 8704
#define GEMM_SMEM (3 * (A_STAGE + B_STAGE))   // 56832

// ---- shared device body (parameterized by runtime ldb / softmax flag) ----
template <typename TO>
__device__ __forceinline__ void gemm_body(
    const __half* __restrict__ Ab, const __half* __restrict__ Wb, int ldb,
    const float* __restrict__ bias, int colbase, TO* __restrict__ Cw,
    bool do_softmax, char* dsm)
{
    const uint32_t aS = smem_u32(dsm);
    const uint32_t bS = aS + 3 * A_STAGE;
    const int tid = threadIdx.x;

    auto load_stage = [&](int stg) {
        const int buf = stg % 3;
        const int k0 = stg * BK;
        const uint32_t ab = aS + buf * A_STAGE;
        const uint32_t bb = bS + buf * B_STAGE;
#pragma unroll
        for (int q = 0; q < 2; q++) {
            const int c = tid + q * 256;
            const int row = c >> 2;
            const int ch = c & 3;
            cp16(ab + (uint32_t)(row * A_ROWB + ch * 16),
                 Ab + (size_t)row * C_DIM + k0 + ch * 8);
        }
#pragma unroll
        for (int q = 0; q < 2; q++) {
            const int c = tid + q * 256;
            const int row = c >> 4;
            const int ch = c & 15;
            cp16(bb + (uint32_t)(row * B_ROWB + ch * 16),
                 Wb + (size_t)(k0 + row) * ldb + ch * 8);
        }
        CP_COMMIT();
    };

    const int wid  = tid >> 5;
    const int lane = tid & 31;
    const int wm = (wid >> 1) * 32;
    const int wn = (wid & 1) * 64;
    const int g  = lane >> 2;
    const int tg = lane & 3;

    const int l7 = lane & 7;
    const int q1 = (lane >> 3) & 1;
    const int q2 = lane >> 4;
    const uint32_t aLane = aS + (uint32_t)((wm + l7 + q1 * 8) * A_ROWB + q2 * 16);
    const uint32_t bLane = bS + (uint32_t)((l7 + q1 * 8) * B_ROWB + q2 * 16 + wn * 2);

    float acc[2][8][4];
#pragma unroll
    for (int i = 0; i < 2; i++)
#pragma unroll
        for (int j = 0; j < 8; j++)
#pragma unroll
            for (int t = 0; t < 4; t++) acc[i][j][t] = 0.f;

    load_stage(0);
    load_stage(1);

    for (int i = 0; i < NSTG; i++) {
        if (i < NSTG - 1) asm volatile("cp.async.wait_group 1;" ::: "memory");
        else              asm volatile("cp.async.wait_group 0;" ::: "memory");
        __syncthreads();
        if (i + 2 < NSTG) load_stage(i + 2);

        const int buf = i % 3;
        const uint32_t aBuf = aLane + buf * A_STAGE;
        const uint32_t bBuf = bLane + buf * B_STAGE;
#pragma unroll
        for (int kk = 0; kk < 2; kk++) {
            uint32_t a[2][4];
#pragma unroll
            for (int mt = 0; mt < 2; mt++)
                LDSM4(a[mt][0], a[mt][1], a[mt][2], a[mt][3],
                      aBuf + (uint32_t)(mt * 16 * A_ROWB + kk * 32));
            uint32_t b[8][2];
#pragma unroll
            for (int np = 0; np < 4; np++)
                LDSM4T(b[2 * np][0], b[2 * np][1], b[2 * np + 1][0], b[2 * np + 1][1],
                       bBuf + (uint32_t)(kk * 16 * B_ROWB + np * 32));
#pragma unroll
            for (int mt = 0; mt < 2; mt++)
#pragma unroll
                for (int nt = 0; nt < 8; nt++)
                    mma_f16(acc[mt][nt], a[mt], b[nt]);
        }
    }

    // ---- epilogue ----
    float bc[8][2];
#pragma unroll
    for (int nt = 0; nt < 8; nt++) {
        const int col = colbase + wn + nt * 8 + tg * 2;
        bc[nt][0] = __ldg(bias + col);
        bc[nt][1] = __ldg(bias + col + 1);
    }
#pragma unroll
    for (int mt = 0; mt < 2; mt++)
#pragma unroll
        for (int nt = 0; nt < 8; nt++) {
            acc[mt][nt][0] += bc[nt][0];
            acc[mt][nt][1] += bc[nt][1];
            acc[mt][nt][2] += bc[nt][0];
            acc[mt][nt][3] += bc[nt][1];
        }

    if (do_softmax) {
#pragma unroll
        for (int mt = 0; mt < 2; mt++) {
            float mxA = -1e30f, mxB = -1e30f;
#pragma unroll
            for (int nt = 0; nt < 8; nt++) {
                mxA = fmaxf(mxA, fmaxf(acc[mt][nt][0], acc[mt][nt][1]));
                mxB = fmaxf(mxB, fmaxf(acc[mt][nt][2], acc[mt][nt][3]));
            }
            mxA = fmaxf(mxA, __shfl_xor_sync(~0u, mxA, 1));
            mxA = fmaxf(mxA, __shfl_xor_sync(~0u, mxA, 2));
            mxB = fmaxf(mxB, __shfl_xor_sync(~0u, mxB, 1));
            mxB = fmaxf(mxB, __shfl_xor_sync(~0u, mxB, 2));
            float sA_ = 0.f, sB_ = 0.f;
#pragma unroll
            for (int nt = 0; nt < 8; nt++) {
                acc[mt][nt][0] = __expf(acc[mt][nt][0] - mxA);
                acc[mt][nt][1] = __expf(acc[mt][nt][1] - mxA);
                acc[mt][nt][2] = __expf(acc[mt][nt][2] - mxB);
                acc[mt][nt][3] = __expf(acc[mt][nt][3] - mxB);
                sA_ += acc[mt][nt][0] + acc[mt][nt][1];
                sB_ += acc[mt][nt][2] + acc[mt][nt][3];
            }
            sA_ += __shfl_xor_sync(~0u, sA_, 1);
            sA_ += __shfl_xor_sync(~0u, sA_, 2);
            sB_ += __shfl_xor_sync(~0u, sB_, 1);
            sB_ += __shfl_xor_sync(~0u, sB_, 2);
            const float invA = 1.0f / sA_;
            const float invB = 1.0f / sB_;
#pragma unroll
            for (int nt = 0; nt < 8; nt++) {
                acc[mt][nt][0] *= invA;
                acc[mt][nt][1] *= invA;
                acc[mt][nt][2] *= invB;
                acc[mt][nt][3] *= invB;
            }
        }
    }

#pragma unroll
    for (int nt = 0; nt < 8; nt++) {
        const int col = colbase + wn + nt * 8 + tg * 2;
#pragma unroll
        for (int mt = 0; mt < 2; mt++) {
            const size_t r0 = (size_t)blockIdx.y * 128 + wm + mt * 16 + g;
            store_pair(Cw + r0 * C_DIM + col, acc[mt][nt][0], acc[mt][nt][1]);
            store_pair(Cw + (r0 + 8) * C_DIM + col, acc[mt][nt][2], acc[mt][nt][3]);
        }
    }
}

// Standard GEMM (Q projection, final projection)
template <bool DO_SOFTMAX, typename TO>
__global__ __launch_bounds__(256, 2) void gemm_mma(
    const __half* __restrict__ A, const __half* __restrict__ W,
    const float* __restrict__ bias, TO* __restrict__ Cw)
{
    extern __shared__ char dsm[];
    gemm_body<TO>(A + (size_t)blockIdx.y * 128 * C_DIM,
                  W + blockIdx.x * 128, C_DIM,
                  bias, blockIdx.x * 128, Cw, DO_SOFTMAX, dsm);
}

// Fused K+V GEMM over packed [512 x 1024] Wkv. bx 0..3 -> K (softmax),
// bx 4..7 -> V (plain). Reads y once for both.
__global__ __launch_bounds__(256, 2) void gemm_kv(
    const __half* __restrict__ A,
    const float* __restrict__ bk, const float* __restrict__ bv,
    __half* __restrict__ Kh, __half* __restrict__ Vh)
{
    extern __shared__ char dsm[];
    const int bx = blockIdx.x;
    const bool isK = bx < 4;
    const __half* Wkv = (const __half*)g_Wkv;
    gemm_body<__half>(A + (size_t)blockIdx.y * 128 * C_DIM,
                      Wkv + bx * 128, 1024,
                      isK ? bk : bv, (bx & 3) * 128,
                      isK ? Kh : Vh, isK, dsm);
}

// ---------------------------------------------------------------------------
// kv partials with fp16 mma: per (bh, chunk of 512 rows) accumulate K^T V
// (64x64 fp32) + column sums of K (parallelized 4x across 256 threads).
// ---------------------------------------------------------------------------
#define KV_PITCHB 144
#define KV_SLABB  (128 * KV_PITCHB)      // 18432
#define KV_SMEM   (2 * 2 * KV_SLABB)     // 73728

__global__ __launch_bounds__(256) void kv_partial_k()
{
    extern __shared__ char dsm[];
    __shared__ float ksred[4][64];
    const uint32_t sbase = smem_u32(dsm);
    const int bh = blockIdx.x, chunk = blockIdx.y;
    const int b = bh >> 3, h = bh & 7;
    const int tid = threadIdx.x;
    const __half* Kb = g_Kh + ((size_t)b * M_DIM + chunk * CH2) * C_DIM + h * D_DIM;
    const __half* Vb = g_Vh + ((size_t)b * M_DIM + chunk * CH2) * C_DIM + h * D_DIM;

    auto load_slab = [&](int s) {
        const int buf = s & 1;
        const uint32_t kd = sbase + buf * (2 * KV_SLABB);
        const uint32_t vd = kd + KV_SLABB;
        const int m0 = s * 128;
#pragma unroll
        for (int q = 0; q < 4; q++) {
            const int c = tid + q * 256;
            const int row = c >> 3, ch = c & 7;
            cp16(kd + (uint32_t)(row * KV_PITCHB + ch * 16),
                 Kb + (size_t)(m0 + row) * C_DIM + ch * 8);
            cp16(vd + (uint32_t)(row * KV_PITCHB + ch * 16),
                 Vb + (size_t)(m0 + row) * C_DIM + ch * 8);
        }
        CP_COMMIT();
    };

    const int wid = tid >> 5, lane = tid & 31;
    const int wd = wid >> 2, we = wid & 3;
    const int d0 = wd * 32, e0 = we * 16;
    const int g = lane >> 2, tg = lane & 3;
    const int l7 = lane & 7, q1 = (lane >> 3) & 1, q2 = lane >> 4;

    float acc[2][2][4] = {};

    load_slab(0);
    load_slab(1);

    // ksum partial: 4 row-groups x 64 cols, coalesced global reads
    {
        const int col = tid & 63, rg = tid >> 6;
        float ssum = 0.f;
        const __half* kp = Kb + (size_t)rg * 128 * C_DIM + col;
#pragma unroll 8
        for (int m = 0; m < 128; m++)
            ssum += __half2float(kp[(size_t)m * C_DIM]);
        ksred[rg][col] = ssum;
    }

    const int NSLAB = CH2 / 128;   // 4
    for (int s = 0; s < NSLAB; s++) {
        if (s < NSLAB - 1) asm volatile("cp.async.wait_group 1;" ::: "memory");
        else               asm volatile("cp.async.wait_group 0;" ::: "memory");
        __syncthreads();
        const int buf = s & 1;
        const uint32_t kS = sbase + buf * (2 * KV_SLABB);
        const uint32_t vS = kS + KV_SLABB;
#pragma unroll
        for (int kk = 0; kk < 8; kk++) {
            const int k0 = kk * 16;
            uint32_t a[2][4];
#pragma unroll
            for (int mt = 0; mt < 2; mt++) {
                const uint32_t addr = kS + (uint32_t)((k0 + l7 + q2 * 8) * KV_PITCHB
                                     + (d0 + mt * 16 + q1 * 8) * 2);
                LDSM4T(a[mt][0], a[mt][1], a[mt][2], a[mt][3], addr);
            }
            uint32_t bfr[2][2];
            {
                const uint32_t addr = vS + (uint32_t)((k0 + l7 + q1 * 8) * KV_PITCHB
                                     + (e0 + q2 * 8) * 2);
                LDSM4T(bfr[0][0], bfr[0][1], bfr[1][0], bfr[1][1], addr);
            }
#pragma unroll
            for (int mt = 0; mt < 2; mt++)
#pragma unroll
                for (int nt = 0; nt < 2; nt++)
                    mma_f16(acc[mt][nt], a[mt], bfr[nt]);
        }
        __syncthreads();
        if (s + 2 < NSLAB) load_slab(s + 2);
    }

    float* dst = g_kvp + ((size_t)bh * NCH2 + chunk) * (D_DIM * D_DIM);
#pragma unroll
    for (int mt = 0; mt < 2; mt++)
#pragma unroll
        for (int nt = 0; nt < 2; nt++) {
            const int d = d0 + mt * 16 + g;
            const int e = e0 + nt * 8 + tg * 2;
            *(float2*)(dst + d * 64 + e)       = make_float2(acc[mt][nt][0], acc[mt][nt][1]);
            *(float2*)(dst + (d + 8) * 64 + e) = make_float2(acc[mt][nt][2], acc[mt][nt][3]);
        }

    if (tid < 64)
        g_ksp[((size_t)bh * NCH2 + chunk) * D_DIM + tid] =
            ksred[0][tid] + ksred[1][tid] + ksred[2][tid] + ksred[3][tid];
}

__global__ __launch_bounds__(256) void kv_reduce_k()
{
    const int bh = blockIdx.x;
    const int i = blockIdx.y * 256 + threadIdx.x;
    const float* src = g_kvp + (size_t)bh * NCH2 * (D_DIM * D_DIM) + i;
    float s = 0.f;
#pragma unroll
    for (int c = 0; c < NCH2; c++) s += src[(size_t)c * (D_DIM * D_DIM)];
    g_kv[bh * (D_DIM * D_DIM) + i] = s;
    if (blockIdx.y == 0 && threadIdx.x < 64) {
        const float* sp = g_ksp + (size_t)bh * NCH2 * D_DIM + threadIdx.x;
        float t = 0.f;
#pragma unroll
        for (int c = 0; c < NCH2; c++) t += sp[c * D_DIM];
        g_ksum[bh * D_DIM + threadIdx.x] = t;
    }
}

// ---------------------------------------------------------------------------
// Attention core: ATT = q @ kv / denom + q   (fp16 in, fp16 out)
// ---------------------------------------------------------------------------
__global__ __launch_bounds__(256) void attn_k()
{
    const int bh = blockIdx.x;
    const int b = bh >> 3, h = bh & 7;
    const int n0 = blockIdx.y * 64;
    __shared__ float kvs[64][64];
    __shared__ float ksums[64];
    __shared__ float qs[64][68];
    const int tid = threadIdx.x;

    {
        const float* kvsrc = g_kv + bh * (D_DIM * D_DIM);
        for (int i = tid; i < 1024; i += 256) {
            int d = i >> 4, c4 = (i & 15) << 2;
            *(float4*)&kvs[d][c4] = *(const float4*)(kvsrc + d * 64 + c4);
        }
        const __half* Qb = g_Qh + ((size_t)b * N_DIM + n0) * C_DIM + h * D_DIM;
        for (int i = tid; i < 1024; i += 256) {
            int m = i >> 4, c4 = (i & 15) << 2;
            uint2 raw = *(const uint2*)(Qb + (size_t)m * C_DIM + c4);
            float2 f0 = __half22float2(*(__half2*)&raw.x);
            float2 f1 = __half22float2(*(__half2*)&raw.y);
            qs[m][c4] = f0.x; qs[m][c4 + 1] = f0.y;
            qs[m][c4 + 2] = f1.x; qs[m][c4 + 3] = f1.y;
        }
        if (tid < 64) ksums[tid] = g_ksum[bh * D_DIM + tid];
    }
    __syncthreads();

    const int r  = tid >> 2;
    const int e0 = (tid & 3) << 4;

    float denom = 0.f;
#pragma unroll
    for (int d = 0; d < 64; d++) denom += qs[r][d] * ksums[d];
    denom = fmaxf(denom, 1e-6f);
    const float inv = 1.0f / denom;

    float acc[16] = {};
    for (int d = 0; d < 64; d++) {
        float qd = qs[r][d];
#pragma unroll
        for (int j = 0; j < 16; j++) acc[j] += qd * kvs[d][e0 + j];
    }

    __half* Ob = g_ATTh + ((size_t)b * N_DIM + n0 + r) * C_DIM + h * D_DIM + e0;
#pragma unroll
    for (int j = 0; j < 16; j += 2) {
        float v0 = acc[j + 0] * inv + qs[r][e0 + j + 0];
        float v1 = acc[j + 1] * inv + qs[r][e0 + j + 1];
        *(__half2*)(Ob + j) = __floats2half2_rn(v0, v1);
    }
}

// ---------------------------------------------------------------------------
// Launch
// ---------------------------------------------------------------------------
template <typename T>
static T* sym_addr(const void* s)
{
    void* p = nullptr;
    cudaGetSymbolAddress(&p, s);
    return (T*)p;
}

extern "C" void kernel_launch(void* const* d_in, const int* in_sizes, int n_in,
                              void* d_out, int out_size)
{
    const float* x  = (const float*)d_in[0];
    const float* y  = (const float*)d_in[1];
    const float* Wq = (const float*)d_in[2];
    const float* bq = (const float*)d_in[3];
    const float* Wk = (const float*)d_in[4];
    const float* bk = (const float*)d_in[5];
    const float* Wv = (const float*)d_in[6];
    const float* bv = (const float*)d_in[7];
    const float* Wp = (const float*)d_in[8];
    const float* bp = (const float*)d_in[9];
    float* out = (float*)d_out;

    __half* Qh   = sym_addr<__half>(g_Qh);
    __half* Kh   = sym_addr<__half>(g_Kh);
    __half* Vh   = sym_addr<__half>(g_Vh);
    __half* xh   = sym_addr<__half>(g_xh);
    __half* yh   = sym_addr<__half>(g_yh);
    __half* ATTh = sym_addr<__half>(g_ATTh);
    __half* Wqp  = sym_addr<__half>(g_Wqp);
    __half* Wkv  = sym_addr<__half>(g_Wkv);

    cudaFuncSetAttribute((const void*)gemm_mma<true, __half>,
                         cudaFuncAttributeMaxDynamicSharedMemorySize, GEMM_SMEM);
    cudaFuncSetAttribute((const void*)gemm_mma<false, float>,
                         cudaFuncAttributeMaxDynamicSharedMemorySize, GEMM_SMEM);
    cudaFuncSetAttribute((const void*)gemm_kv,
                         cudaFuncAttributeMaxDynamicSharedMemorySize, GEMM_SMEM);
    cudaFuncSetAttribute((const void*)kv_partial_k,
                         cudaFuncAttributeMaxDynamicSharedMemorySize, KV_SMEM);

    // fp16 conversion pre-passes (3 launches)
    const int n4 = (int)((size_t)ROWS * C_DIM / 4);
    cvt_half_k<<<4096, 256>>>((const float4*)x, (__half2*)xh, n4);
    cvt_half_k<<<4096, 256>>>((const float4*)y, (__half2*)yh, n4);
    cvt_w4_k<<<dim3(64, 4), 256>>>((const float4*)Wq, (const float4*)Wk,
                                   (const float4*)Wv, (const float4*)Wp,
                                   Wqp, Wkv);

    dim3 ggrid(C_DIM / 128, ROWS / 128);     // (4, 256)
    dim3 kvgrid(2 * C_DIM / 128, ROWS / 128); // (8, 256)

    // #4: Q projection + softmax
    gemm_mma<true, __half><<<ggrid, 256, GEMM_SMEM>>>(xh, Wqp, bq, Qh);
    // #5: fused K (softmax) + V projection, reads y once
    gemm_kv<<<kvgrid, 256, GEMM_SMEM>>>(yh, bk, bv, Kh, Vh);
    // #6: kv_partial (now in ncu's profiled slot)
    kv_partial_k<<<dim3(BH, NCH2), 256, KV_SMEM>>>();
    kv_reduce_k<<<dim3(BH, 16), 256>>>();
    attn_k<<<dim3(BH, N_DIM / 64), 256>>>();
    gemm_mma<false, float><<<ggrid, 256, GEMM_SMEM>>>(ATTh, Wqp + C_DIM * C_DIM, bp, out);
}

// round 17
// speedup vs baseline: 1.8204x; 1.7600x over previous
#include <cuda_runtime.h>
#include <cuda_fp16.h>
#include <cstdint>
#include <math.h>

// Problem constants
#define B_DIM 4
#define N_DIM 8192
#define M_DIM 8192
#define C_DIM 512
#define H_DIM 8
#define D_DIM 64
#define BH    (B_DIM * H_DIM)     // 32
#define ROWS  (B_DIM * N_DIM)     // 32768

// kv chunking
#define CH2   512
#define NCH2  (M_DIM / CH2)       // 16

// ---------------------------------------------------------------------------
// Scratch (device globals; no allocation in kernel_launch)
// ---------------------------------------------------------------------------
__device__ __half g_Qh [(size_t)B_DIM * N_DIM * C_DIM];
__device__ __half g_Kh [(size_t)B_DIM * M_DIM * C_DIM];
__device__ __half g_Vh [(size_t)B_DIM * M_DIM * C_DIM];
__device__ __half g_xh [(size_t)B_DIM * N_DIM * C_DIM];
__device__ __half g_yh [(size_t)B_DIM * M_DIM * C_DIM];
__device__ __half g_ATTh[(size_t)B_DIM * N_DIM * C_DIM];
__device__ __half g_Wqp [2 * C_DIM * C_DIM];          // Wq, Wp
__device__ __half g_Wkv [C_DIM * 2 * C_DIM];          // [512 rows][Wk|Wv cols]
__device__ float  g_kvp [(size_t)BH * NCH2 * D_DIM * D_DIM];
__device__ float  g_ksp [(size_t)BH * NCH2 * D_DIM];
__device__ __half g_kvh [BH * D_DIM * D_DIM];
__device__ float  g_ksum[BH * D_DIM];

// ---------------------------------------------------------------------------
// Helpers
// ---------------------------------------------------------------------------
__device__ __forceinline__ void cp16(uint32_t dst, const void* src) {
    asm volatile("cp.async.cg.shared.global [%0], [%1], 16;" :: "r"(dst), "l"(src));
}
__device__ __forceinline__ uint32_t smem_u32(const void* p) {
    uint32_t a;
    asm("{ .reg .u64 t; cvta.to.shared.u64 t, %1; cvt.u32.u64 %0, t; }"
        : "=r"(a) : "l"(p));
    return a;
}
#define CP_COMMIT() asm volatile("cp.async.commit_group;" ::: "memory")

#define LDSM4(r0, r1, r2, r3, addr) \
    asm volatile("ldmatrix.sync.aligned.m8n8.x4.shared.b16 {%0,%1,%2,%3}, [%4];" \
        : "=r"(r0), "=r"(r1), "=r"(r2), "=r"(r3) : "r"(addr))
#define LDSM4T(r0, r1, r2, r3, addr) \
    asm volatile("ldmatrix.sync.aligned.m8n8.x4.trans.shared.b16 {%0,%1,%2,%3}, [%4];" \
        : "=r"(r0), "=r"(r1), "=r"(r2), "=r"(r3) : "r"(addr))

__device__ __forceinline__ void mma_f16(
    float c[4], const uint32_t a[4], const uint32_t b[2])
{
    asm volatile(
        "mma.sync.aligned.m16n8k16.row.col.f32.f16.f16.f32 "
        "{%0,%1,%2,%3}, {%4,%5,%6,%7}, {%8,%9}, {%0,%1,%2,%3};"
        : "+f"(c[0]), "+f"(c[1]), "+f"(c[2]), "+f"(c[3])
        : "r"(a[0]), "r"(a[1]), "r"(a[2]), "r"(a[3]), "r"(b[0]), "r"(b[1]));
}

__device__ __forceinline__ void store_pair(float* p, float a, float b) {
    *(float2*)p = make_float2(a, b);
}
__device__ __forceinline__ void store_pair(__half* p, float a, float b) {
    *(__half2*)p = __floats2half2_rn(a, b);
}

// ---------------------------------------------------------------------------
// fp32 -> fp16 conversion pre-passes
// ---------------------------------------------------------------------------
__global__ __launch_bounds__(256) void cvt_half_k(
    const float4* __restrict__ in, __half2* __restrict__ out, int n4)
{
    int i = blockIdx.x * blockDim.x + threadIdx.x;
    const int stride = gridDim.x * blockDim.x;
    for (; i < n4; i += stride) {
        float4 v = in[i];
        out[i * 2]     = __floats2half2_rn(v.x, v.y);
        out[i * 2 + 1] = __floats2half2_rn(v.z, v.w);
    }
}

// Weight conversion: Wq,Wp -> g_Wqp (contiguous); Wk,Wv -> g_Wkv packed
// as [512 rows][1024 cols] = [Wk row | Wv row].
__global__ __launch_bounds__(256) void cvt_w4_k(
    const float4* __restrict__ wq, const float4* __restrict__ wk,
    const float4* __restrict__ wv, const float4* __restrict__ wp,
    __half* __restrict__ wqp, __half* __restrict__ wkv)
{
    const int slot = blockIdx.y;   // 0=Wq, 1=Wp, 2=Wk, 3=Wv
    const float4* in = (slot == 0) ? wq : (slot == 1) ? wp : (slot == 2) ? wk : wv;
    const int n4 = C_DIM * C_DIM / 4;
    for (int i = blockIdx.x * 256 + threadIdx.x; i < n4; i += gridDim.x * 256) {
        float4 v = in[i];
        __half2 h0 = __floats2half2_rn(v.x, v.y);
        __half2 h1 = __floats2half2_rn(v.z, v.w);
        if (slot < 2) {
            __half2* o = (__half2*)(wqp + (size_t)slot * C_DIM * C_DIM) + i * 2;
            o[0] = h0; o[1] = h1;
        } else {
            const int e = i * 4;
            const int k = e >> 9;
            const int n = e & 511;
            __half2* o = (__half2*)(wkv + (size_t)k * 1024 + n + (slot == 3 ? 512 : 0));
            o[0] = h0; o[1] = h1;
        }
    }
}

// ---------------------------------------------------------------------------
// GEMM: block 128x128, BK=32, 3-stage cp.async (proven config).
// ---------------------------------------------------------------------------
#define BK       32
#define NSTG     (C_DIM / BK)     // 16
#define A_ROWB   80
#define B_ROWB   272
#define A_STAGE  (128 * A_ROWB)   // 10240
#define B_STAGE  (BK * B_ROWB)    // 8704
#define GEMM_SMEM (3 * (A_STAGE + B_STAGE))   // 56832

template <typename TO>
__device__ __forceinline__ void gemm_body(
    const __half* __restrict__ Ab, const __half* __restrict__ Wb, int ldb,
    const float* __restrict__ bias, int colbase, TO* __restrict__ Cw,
    bool do_softmax, char* dsm)
{
    const uint32_t aS = smem_u32(dsm);
    const uint32_t bS = aS + 3 * A_STAGE;
    const int tid = threadIdx.x;

    auto load_stage = [&](int stg) {
        const int buf = stg % 3;
        const int k0 = stg * BK;
        const uint32_t ab = aS + buf * A_STAGE;
        const uint32_t bb = bS + buf * B_STAGE;
#pragma unroll
        for (int q = 0; q < 2; q++) {
            const int c = tid + q * 256;
            const int row = c >> 2;
            const int ch = c & 3;
            cp16(ab + (uint32_t)(row * A_ROWB + ch * 16),
                 Ab + (size_t)row * C_DIM + k0 + ch * 8);
        }
#pragma unroll
        for (int q = 0; q < 2; q++) {
            const int c = tid + q * 256;
            const int row = c >> 4;
            const int ch = c & 15;
            cp16(bb + (uint32_t)(row * B_ROWB + ch * 16),
                 Wb + (size_t)(k0 + row) * ldb + ch * 8);
        }
        CP_COMMIT();
    };

    const int wid  = tid >> 5;
    const int lane = tid & 31;
    const int wm = (wid >> 1) * 32;
    const int wn = (wid & 1) * 64;
    const int g  = lane >> 2;
    const int tg = lane & 3;

    const int l7 = lane & 7;
    const int q1 = (lane >> 3) & 1;
    const int q2 = lane >> 4;
    const uint32_t aLane = aS + (uint32_t)((wm + l7 + q1 * 8) * A_ROWB + q2 * 16);
    const uint32_t bLane = bS + (uint32_t)((l7 + q1 * 8) * B_ROWB + q2 * 16 + wn * 2);

    float acc[2][8][4];
#pragma unroll
    for (int i = 0; i < 2; i++)
#pragma unroll
        for (int j = 0; j < 8; j++)
#pragma unroll
            for (int t = 0; t < 4; t++) acc[i][j][t] = 0.f;

    load_stage(0);
    load_stage(1);

    for (int i = 0; i < NSTG; i++) {
        if (i < NSTG - 1) asm volatile("cp.async.wait_group 1;" ::: "memory");
        else              asm volatile("cp.async.wait_group 0;" ::: "memory");
        __syncthreads();
        if (i + 2 < NSTG) load_stage(i + 2);

        const int buf = i % 3;
        const uint32_t aBuf = aLane + buf * A_STAGE;
        const uint32_t bBuf = bLane + buf * B_STAGE;
#pragma unroll
        for (int kk = 0; kk < 2; kk++) {
            uint32_t a[2][4];
#pragma unroll
            for (int mt = 0; mt < 2; mt++)
                LDSM4(a[mt][0], a[mt][1], a[mt][2], a[mt][3],
                      aBuf + (uint32_t)(mt * 16 * A_ROWB + kk * 32));
            uint32_t b[8][2];
#pragma unroll
            for (int np = 0; np < 4; np++)
                LDSM4T(b[2 * np][0], b[2 * np][1], b[2 * np + 1][0], b[2 * np + 1][1],
                       bBuf + (uint32_t)(kk * 16 * B_ROWB + np * 32));
#pragma unroll
            for (int mt = 0; mt < 2; mt++)
#pragma unroll
                for (int nt = 0; nt < 8; nt++)
                    mma_f16(acc[mt][nt], a[mt], b[nt]);
        }
    }

    // ---- epilogue ----
    float bc[8][2];
#pragma unroll
    for (int nt = 0; nt < 8; nt++) {
        const int col = colbase + wn + nt * 8 + tg * 2;
        bc[nt][0] = __ldg(bias + col);
        bc[nt][1] = __ldg(bias + col + 1);
    }
#pragma unroll
    for (int mt = 0; mt < 2; mt++)
#pragma unroll
        for (int nt = 0; nt < 8; nt++) {
            acc[mt][nt][0] += bc[nt][0];
            acc[mt][nt][1] += bc[nt][1];
            acc[mt][nt][2] += bc[nt][0];
            acc[mt][nt][3] += bc[nt][1];
        }

    if (do_softmax) {
#pragma unroll
        for (int mt = 0; mt < 2; mt++) {
            float mxA = -1e30f, mxB = -1e30f;
#pragma unroll
            for (int nt = 0; nt < 8; nt++) {
                mxA = fmaxf(mxA, fmaxf(acc[mt][nt][0], acc[mt][nt][1]));
                mxB = fmaxf(mxB, fmaxf(acc[mt][nt][2], acc[mt][nt][3]));
            }
            mxA = fmaxf(mxA, __shfl_xor_sync(~0u, mxA, 1));
            mxA = fmaxf(mxA, __shfl_xor_sync(~0u, mxA, 2));
            mxB = fmaxf(mxB, __shfl_xor_sync(~0u, mxB, 1));
            mxB = fmaxf(mxB, __shfl_xor_sync(~0u, mxB, 2));
            float sA_ = 0.f, sB_ = 0.f;
#pragma unroll
            for (int nt = 0; nt < 8; nt++) {
                acc[mt][nt][0] = __expf(acc[mt][nt][0] - mxA);
                acc[mt][nt][1] = __expf(acc[mt][nt][1] - mxA);
                acc[mt][nt][2] = __expf(acc[mt][nt][2] - mxB);
                acc[mt][nt][3] = __expf(acc[mt][nt][3] - mxB);
                sA_ += acc[mt][nt][0] + acc[mt][nt][1];
                sB_ += acc[mt][nt][2] + acc[mt][nt][3];
            }
            sA_ += __shfl_xor_sync(~0u, sA_, 1);
            sA_ += __shfl_xor_sync(~0u, sA_, 2);
            sB_ += __shfl_xor_sync(~0u, sB_, 1);
            sB_ += __shfl_xor_sync(~0u, sB_, 2);
            const float invA = 1.0f / sA_;
            const float invB = 1.0f / sB_;
#pragma unroll
            for (int nt = 0; nt < 8; nt++) {
                acc[mt][nt][0] *= invA;
                acc[mt][nt][1] *= invA;
                acc[mt][nt][2] *= invB;
                acc[mt][nt][3] *= invB;
            }
        }
    }

#pragma unroll
    for (int nt = 0; nt < 8; nt++) {
        const int col = colbase + wn + nt * 8 + tg * 2;
#pragma unroll
        for (int mt = 0; mt < 2; mt++) {
            const size_t r0 = (size_t)blockIdx.y * 128 + wm + mt * 16 + g;
            store_pair(Cw + r0 * C_DIM + col, acc[mt][nt][0], acc[mt][nt][1]);
            store_pair(Cw + (r0 + 8) * C_DIM + col, acc[mt][nt][2], acc[mt][nt][3]);
        }
    }
}

template <bool DO_SOFTMAX, typename TO>
__global__ __launch_bounds__(256, 2) void gemm_mma(
    const __half* __restrict__ A, const __half* __restrict__ W,
    const float* __restrict__ bias, TO* __restrict__ Cw)
{
    extern __shared__ char dsm[];
    gemm_body<TO>(A + (size_t)blockIdx.y * 128 * C_DIM,
                  W + blockIdx.x * 128, C_DIM,
                  bias, blockIdx.x * 128, Cw, DO_SOFTMAX, dsm);
}

__global__ __launch_bounds__(256, 2) void gemm_kv(
    const __half* __restrict__ A,
    const float* __restrict__ bk, const float* __restrict__ bv,
    __half* __restrict__ Kh, __half* __restrict__ Vh)
{
    extern __shared__ char dsm[];
    const int bx = blockIdx.x;
    const bool isK = bx < 4;
    const __half* Wkv = (const __half*)g_Wkv;
    gemm_body<__half>(A + (size_t)blockIdx.y * 128 * C_DIM,
                      Wkv + bx * 128, 1024,
                      isK ? bk : bv, (bx & 3) * 128,
                      isK ? Kh : Vh, isK, dsm);
}

// ---------------------------------------------------------------------------
// kv partials with fp16 mma (+ parallel ksum)
// ---------------------------------------------------------------------------
#define KV_PITCHB 144
#define KV_SLABB  (128 * KV_PITCHB)      // 18432
#define KV_SMEM   (2 * 2 * KV_SLABB)     // 73728

__global__ __launch_bounds__(256) void kv_partial_k()
{
    extern __shared__ char dsm[];
    __shared__ float ksred[4][64];
    const uint32_t sbase = smem_u32(dsm);
    const int bh = blockIdx.x, chunk = blockIdx.y;
    const int b = bh >> 3, h = bh & 7;
    const int tid = threadIdx.x;
    const __half* Kb = g_Kh + ((size_t)b * M_DIM + chunk * CH2) * C_DIM + h * D_DIM;
    const __half* Vb = g_Vh + ((size_t)b * M_DIM + chunk * CH2) * C_DIM + h * D_DIM;

    auto load_slab = [&](int s) {
        const int buf = s & 1;
        const uint32_t kd = sbase + buf * (2 * KV_SLABB);
        const uint32_t vd = kd + KV_SLABB;
        const int m0 = s * 128;
#pragma unroll
        for (int q = 0; q < 4; q++) {
            const int c = tid + q * 256;
            const int row = c >> 3, ch = c & 7;
            cp16(kd + (uint32_t)(row * KV_PITCHB + ch * 16),
                 Kb + (size_t)(m0 + row) * C_DIM + ch * 8);
            cp16(vd + (uint32_t)(row * KV_PITCHB + ch * 16),
                 Vb + (size_t)(m0 + row) * C_DIM + ch * 8);
        }
        CP_COMMIT();
    };

    const int wid = tid >> 5, lane = tid & 31;
    const int wd = wid >> 2, we = wid & 3;
    const int d0 = wd * 32, e0 = we * 16;
    const int g = lane >> 2, tg = lane & 3;
    const int l7 = lane & 7, q1 = (lane >> 3) & 1, q2 = lane >> 4;

    float acc[2][2][4] = {};

    load_slab(0);
    load_slab(1);

    {
        const int col = tid & 63, rg = tid >> 6;
        float ssum = 0.f;
        const __half* kp = Kb + (size_t)rg * 128 * C_DIM + col;
#pragma unroll 8
        for (int m = 0; m < 128; m++)
            ssum += __half2float(kp[(size_t)m * C_DIM]);
        ksred[rg][col] = ssum;
    }

    const int NSLAB = CH2 / 128;   // 4
    for (int s = 0; s < NSLAB; s++) {
        if (s < NSLAB - 1) asm volatile("cp.async.wait_group 1;" ::: "memory");
        else               asm volatile("cp.async.wait_group 0;" ::: "memory");
        __syncthreads();
        const int buf = s & 1;
        const uint32_t kS = sbase + buf * (2 * KV_SLABB);
        const uint32_t vS = kS + KV_SLABB;
#pragma unroll
        for (int kk = 0; kk < 8; kk++) {
            const int k0 = kk * 16;
            uint32_t a[2][4];
#pragma unroll
            for (int mt = 0; mt < 2; mt++) {
                const uint32_t addr = kS + (uint32_t)((k0 + l7 + q2 * 8) * KV_PITCHB
                                     + (d0 + mt * 16 + q1 * 8) * 2);
                LDSM4T(a[mt][0], a[mt][1], a[mt][2], a[mt][3], addr);
            }
            uint32_t bfr[2][2];
            {
                const uint32_t addr = vS + (uint32_t)((k0 + l7 + q1 * 8) * KV_PITCHB
                                     + (e0 + q2 * 8) * 2);
                LDSM4T(bfr[0][0], bfr[0][1], bfr[1][0], bfr[1][1], addr);
            }
#pragma unroll
            for (int mt = 0; mt < 2; mt++)
#pragma unroll
                for (int nt = 0; nt < 2; nt++)
                    mma_f16(acc[mt][nt], a[mt], bfr[nt]);
        }
        __syncthreads();
        if (s + 2 < NSLAB) load_slab(s + 2);
    }

    float* dst = g_kvp + ((size_t)bh * NCH2 + chunk) * (D_DIM * D_DIM);
#pragma unroll
    for (int mt = 0; mt < 2; mt++)
#pragma unroll
        for (int nt = 0; nt < 2; nt++) {
            const int d = d0 + mt * 16 + g;
            const int e = e0 + nt * 8 + tg * 2;
            *(float2*)(dst + d * 64 + e)       = make_float2(acc[mt][nt][0], acc[mt][nt][1]);
            *(float2*)(dst + (d + 8) * 64 + e) = make_float2(acc[mt][nt][2], acc[mt][nt][3]);
        }

    if (tid < 64)
        g_ksp[((size_t)bh * NCH2 + chunk) * D_DIM + tid] =
            ksred[0][tid] + ksred[1][tid] + ksred[2][tid] + ksred[3][tid];
}

// Reduce partials -> fp16 kv + fp32 ksum
__global__ __launch_bounds__(256) void kv_reduce_k()
{
    const int bh = blockIdx.x;
    const int i = blockIdx.y * 256 + threadIdx.x;
    const float* src = g_kvp + (size_t)bh * NCH2 * (D_DIM * D_DIM) + i;
    float s = 0.f;
#pragma unroll
    for (int c = 0; c < NCH2; c++) s += src[(size_t)c * (D_DIM * D_DIM)];
    g_kvh[bh * (D_DIM * D_DIM) + i] = __float2half(s);
    if (blockIdx.y == 0 && threadIdx.x < 64) {
        const float* sp = g_ksp + (size_t)bh * NCH2 * D_DIM + threadIdx.x;
        float t = 0.f;
#pragma unroll
        for (int c = 0; c < NCH2; c++) t += sp[c * D_DIM];
        g_ksum[bh * D_DIM + threadIdx.x] = t;
    }
}

// ---------------------------------------------------------------------------
// Tensor-core attention: per (bh, 128 rows): ACC = Q[128x64] @ KVE[64x80],
// where KVE = [kv | ksum | 0...]. col 64 of ACC = denom. out = acc/denom + q.
// 128 threads = 4 warps (32 rows each).
// ---------------------------------------------------------------------------
#define AQ_PITCH 144                     // 64 halves + 8 pad
#define AK_PITCH 160                     // 80 halves
#define ATTN_SMEM (128 * AQ_PITCH + 64 * AK_PITCH)   // 18432 + 10240 = 28672

__global__ __launch_bounds__(128) void attn_mma_k()
{
    extern __shared__ char dsm[];
    const int bh = blockIdx.x;
    const int b = bh >> 3, h = bh & 7;
    const int n0 = blockIdx.y * 128;
    const int tid = threadIdx.x;
    const uint32_t qS = smem_u32(dsm);
    const uint32_t kS = qS + 128 * AQ_PITCH;
    __half* kvp = (__half*)(dsm + 128 * AQ_PITCH);

    const __half* Qb = g_Qh + ((size_t)b * N_DIM + n0) * C_DIM + h * D_DIM;

    // Q tile: 128 rows x 64 halves = 1024 x 16B chunks; 8 per thread
#pragma unroll
    for (int q = 0; q < 8; q++) {
        const int c = tid + q * 128;
        const int row = c >> 3, ch = c & 7;
        cp16(qS + (uint32_t)(row * AQ_PITCH + ch * 16),
             Qb + (size_t)row * C_DIM + ch * 8);
    }
    // kv tile: 64 rows x 64 halves = 512 x 16B chunks; 4 per thread
    const __half* kvsrc = g_kvh + bh * (D_DIM * D_DIM);
#pragma unroll
    for (int q = 0; q < 4; q++) {
        const int c = tid + q * 128;
        const int row = c >> 3, ch = c & 7;
        cp16(kS + (uint32_t)(row * AK_PITCH + ch * 16),
             kvsrc + row * 64 + ch * 8);
    }
    CP_COMMIT();

    // ksum col (64) + zero pad cols 65..79 (normal smem stores, disjoint bytes)
    if (tid < 64) {
        __half* rowp = kvp + tid * (AK_PITCH / 2);
        rowp[64] = __float2half(g_ksum[bh * D_DIM + tid]);
#pragma unroll
        for (int j = 65; j < 80; j++) rowp[j] = __float2half(0.f);
    }

    asm volatile("cp.async.wait_group 0;" ::: "memory");
    __syncthreads();

    const int wid = tid >> 5, lane = tid & 31;
    const int wm = wid * 32;
    const int g = lane >> 2, tg = lane & 3;
    const int l7 = lane & 7, q1 = (lane >> 3) & 1, q2 = lane >> 4;

    const uint32_t aLane = qS + (uint32_t)((wm + l7 + q1 * 8) * AQ_PITCH + q2 * 16);
    const uint32_t bLane = kS + (uint32_t)((l7 + q1 * 8) * AK_PITCH + q2 * 16);

    float acc[2][10][4];
#pragma unroll
    for (int i = 0; i < 2; i++)
#pragma unroll
        for (int j = 0; j < 10; j++)
#pragma unroll
            for (int t = 0; t < 4; t++) acc[i][j][t] = 0.f;

#pragma unroll
    for (int kk = 0; kk < 4; kk++) {
        uint32_t a[2][4];
#pragma unroll
        for (int mt = 0; mt < 2; mt++)
            LDSM4(a[mt][0], a[mt][1], a[mt][2], a[mt][3],
                  aLane + (uint32_t)(mt * 16 * AQ_PITCH + kk * 32));
        uint32_t bfr[10][2];
#pragma unroll
        for (int np = 0; np < 5; np++)
            LDSM4T(bfr[2 * np][0], bfr[2 * np][1], bfr[2 * np + 1][0], bfr[2 * np + 1][1],
                   bLane + (uint32_t)(kk * 16 * AK_PITCH + np * 32));
#pragma unroll
        for (int mt = 0; mt < 2; mt++)
#pragma unroll
            for (int nt = 0; nt < 10; nt++)
                mma_f16(acc[mt][nt], a[mt], bfr[nt]);
    }

    // Epilogue: denom from col 64 (n-tile 8, frag 0/2 at tg=0), out = acc/denom + q
    __half* ATTb = g_ATTh + ((size_t)b * N_DIM + n0) * C_DIM + h * D_DIM;
#pragma unroll
    for (int mt = 0; mt < 2; mt++) {
        const float dA = __shfl_sync(~0u, acc[mt][8][0], lane & ~3);
        const float dB = __shfl_sync(~0u, acc[mt][8][2], lane & ~3);
        const float invA = 1.0f / fmaxf(dA, 1e-6f);
        const float invB = 1.0f / fmaxf(dB, 1e-6f);
        const int rA = wm + mt * 16 + g;
        const int rB = rA + 8;
#pragma unroll
        for (int nt = 0; nt < 8; nt++) {
            const int col = nt * 8 + tg * 2;
            float2 qA = __half22float2(*(__half2*)(dsm + rA * AQ_PITCH + col * 2));
            float2 qB = __half22float2(*(__half2*)(dsm + rB * AQ_PITCH + col * 2));
            store_pair(ATTb + (size_t)rA * C_DIM + col,
                       acc[mt][nt][0] * invA + qA.x, acc[mt][nt][1] * invA + qA.y);
            store_pair(ATTb + (size_t)rB * C_DIM + col,
                       acc[mt][nt][2] * invB + qB.x, acc[mt][nt][3] * invB + qB.y);
        }
    }
}

// ---------------------------------------------------------------------------
// Launch
// ---------------------------------------------------------------------------
template <typename T>
static T* sym_addr(const void* s)
{
    void* p = nullptr;
    cudaGetSymbolAddress(&p, s);
    return (T*)p;
}

extern "C" void kernel_launch(void* const* d_in, const int* in_sizes, int n_in,
                              void* d_out, int out_size)
{
    const float* x  = (const float*)d_in[0];
    const float* y  = (const float*)d_in[1];
    const float* Wq = (const float*)d_in[2];
    const float* bq = (const float*)d_in[3];
    const float* Wk = (const float*)d_in[4];
    const float* bk = (const float*)d_in[5];
    const float* Wv = (const float*)d_in[6];
    const float* bv = (const float*)d_in[7];
    const float* Wp = (const float*)d_in[8];
    const float* bp = (const float*)d_in[9];
    float* out = (float*)d_out;

    __half* Qh   = sym_addr<__half>(g_Qh);
    __half* Kh   = sym_addr<__half>(g_Kh);
    __half* Vh   = sym_addr<__half>(g_Vh);
    __half* xh   = sym_addr<__half>(g_xh);
    __half* yh   = sym_addr<__half>(g_yh);
    __half* ATTh = sym_addr<__half>(g_ATTh);
    __half* Wqp  = sym_addr<__half>(g_Wqp);

    cudaFuncSetAttribute((const void*)gemm_mma<true, __half>,
                         cudaFuncAttributeMaxDynamicSharedMemorySize, GEMM_SMEM);
    cudaFuncSetAttribute((const void*)gemm_mma<false, float>,
                         cudaFuncAttributeMaxDynamicSharedMemorySize, GEMM_SMEM);
    cudaFuncSetAttribute((const void*)gemm_kv,
                         cudaFuncAttributeMaxDynamicSharedMemorySize, GEMM_SMEM);
    cudaFuncSetAttribute((const void*)kv_partial_k,
                         cudaFuncAttributeMaxDynamicSharedMemorySize, KV_SMEM);
    cudaFuncSetAttribute((const void*)attn_mma_k,
                         cudaFuncAttributeMaxDynamicSharedMemorySize, ATTN_SMEM);

    const int n4 = (int)((size_t)ROWS * C_DIM / 4);
    cvt_half_k<<<4096, 256>>>((const float4*)x, (__half2*)xh, n4);
    cvt_half_k<<<4096, 256>>>((const float4*)y, (__half2*)yh, n4);
    cvt_w4_k<<<dim3(64, 4), 256>>>((const float4*)Wq, (const float4*)Wk,
                                   (const float4*)Wv, (const float4*)Wp,
                                   Wqp, sym_addr<__half>(g_Wkv));

    dim3 ggrid(C_DIM / 128, ROWS / 128);      // (4, 256)
    dim3 kvgrid(2 * C_DIM / 128, ROWS / 128); // (8, 256)

    gemm_mma<true, __half><<<ggrid, 256, GEMM_SMEM>>>(xh, Wqp, bq, Qh);
    gemm_kv<<<kvgrid, 256, GEMM_SMEM>>>(yh, bk, bv, Kh, Vh);
    kv_partial_k<<<dim3(BH, NCH2), 256, KV_SMEM>>>();
    kv_reduce_k<<<dim3(BH, 16), 256>>>();
    attn_mma_k<<<dim3(BH, N_DIM / 128), 128, ATTN_SMEM>>>();
    gemm_mma<false, float><<<ggrid, 256, GEMM_SMEM>>>(ATTh, Wqp + C_DIM * C_DIM, bp, out);
}